// round 2
// baseline (speedup 1.0000x reference)
#include <cuda_runtime.h>
#include <math.h>

#define NN 50000
#define DF 256
#define INF 128
#define EE 500000
#define QQ 200000
#define BN_EPS 1e-5f

// ---------------- scratch (static device globals; no allocations) ----------------
__device__ float g_h[NN * DF];      // node features (reused across stages)
__device__ float g_m[NN * DF];      // h @ W
__device__ float g_agg[NN * DF];    // neighbor aggregation
__device__ float g_deg[NN];
__device__ float g_dinv[NN];
__device__ double g_sum[DF];
__device__ double g_sumsq[DF];
__device__ float g_scale[DF];
__device__ float g_bias[DF];

// ---------------- degree / dinv ----------------
__global__ void k_zero_deg() {
    int i = blockIdx.x * blockDim.x + threadIdx.x;
    if (i < NN) g_deg[i] = 0.f;
}
__global__ void k_count(const int* __restrict__ adj_row) {
    int e = blockIdx.x * blockDim.x + threadIdx.x;
    if (e < EE) atomicAdd(&g_deg[adj_row[e]], 1.f);
}
__global__ void k_dinv() {
    int i = blockIdx.x * blockDim.x + threadIdx.x;
    if (i < NN) g_dinv[i] = rsqrtf(g_deg[i] + 1.f);
}

// ---------------- h = concat(emb, x) ----------------
__global__ void k_build_h(const float* __restrict__ x, const float* __restrict__ emb) {
    int t = blockIdx.x * blockDim.x + threadIdx.x;
    if (t >= NN * DF) return;
    int n = t >> 8, j = t & 255;
    g_h[t] = (j < INF) ? emb[n * INF + j] : x[n * INF + (j - INF)];
}

__global__ void k_zero_agg() {
    int t = blockIdx.x * blockDim.x + threadIdx.x;
    if (t < NN * DF) g_agg[t] = 0.f;
}

// ---------------- GEMM: g_m = g_h @ W   (A:[NN,256] row-major, W:[256,256]) ----------------
__global__ void k_gemm(const float* __restrict__ W) {
    __shared__ float As[64][33];
    __shared__ float Ws[32][64];
    const int tid = threadIdx.x;                 // 256 threads
    const int row0 = blockIdx.y * 64;
    const int col0 = blockIdx.x * 64;
    const int tx = tid & 15, ty = tid >> 4;

    const int a_r = tid >> 2;                    // 0..63
    const int a_c = (tid & 3) * 4;               // 0,4,8,12 (+16)
    const int w_r = tid >> 3;                    // 0..31
    const int w_c = (tid & 7) * 4;               // 0..28   (+32)

    float acc[4][4];
#pragma unroll
    for (int i = 0; i < 4; i++)
#pragma unroll
        for (int j = 0; j < 4; j++) acc[i][j] = 0.f;

    for (int k0 = 0; k0 < DF; k0 += 32) {
        bool rok = (row0 + a_r) < NN;
        float4 av0 = make_float4(0.f, 0.f, 0.f, 0.f);
        float4 av1 = make_float4(0.f, 0.f, 0.f, 0.f);
        if (rok) {
            const float* ap = &g_h[(row0 + a_r) * DF + k0 + a_c];
            av0 = *(const float4*)(ap);
            av1 = *(const float4*)(ap + 16);
        }
        As[a_r][a_c + 0] = av0.x; As[a_r][a_c + 1] = av0.y;
        As[a_r][a_c + 2] = av0.z; As[a_r][a_c + 3] = av0.w;
        As[a_r][a_c + 16] = av1.x; As[a_r][a_c + 17] = av1.y;
        As[a_r][a_c + 18] = av1.z; As[a_r][a_c + 19] = av1.w;

        const float* wp = &W[(k0 + w_r) * DF + col0 + w_c];
        *(float4*)&Ws[w_r][w_c]      = *(const float4*)(wp);
        *(float4*)&Ws[w_r][w_c + 32] = *(const float4*)(wp + 32);

        __syncthreads();
#pragma unroll
        for (int kk = 0; kk < 32; kk++) {
            float4 b = *(const float4*)&Ws[kk][tx * 4];
            float a0 = As[ty * 4 + 0][kk];
            float a1 = As[ty * 4 + 1][kk];
            float a2 = As[ty * 4 + 2][kk];
            float a3 = As[ty * 4 + 3][kk];
            acc[0][0] = fmaf(a0, b.x, acc[0][0]); acc[0][1] = fmaf(a0, b.y, acc[0][1]);
            acc[0][2] = fmaf(a0, b.z, acc[0][2]); acc[0][3] = fmaf(a0, b.w, acc[0][3]);
            acc[1][0] = fmaf(a1, b.x, acc[1][0]); acc[1][1] = fmaf(a1, b.y, acc[1][1]);
            acc[1][2] = fmaf(a1, b.z, acc[1][2]); acc[1][3] = fmaf(a1, b.w, acc[1][3]);
            acc[2][0] = fmaf(a2, b.x, acc[2][0]); acc[2][1] = fmaf(a2, b.y, acc[2][1]);
            acc[2][2] = fmaf(a2, b.z, acc[2][2]); acc[2][3] = fmaf(a2, b.w, acc[2][3]);
            acc[3][0] = fmaf(a3, b.x, acc[3][0]); acc[3][1] = fmaf(a3, b.y, acc[3][1]);
            acc[3][2] = fmaf(a3, b.z, acc[3][2]); acc[3][3] = fmaf(a3, b.w, acc[3][3]);
        }
        __syncthreads();
    }
#pragma unroll
    for (int i = 0; i < 4; i++) {
        int r = row0 + ty * 4 + i;
        if (r < NN) {
            float4 v = make_float4(acc[i][0], acc[i][1], acc[i][2], acc[i][3]);
            *(float4*)&g_m[r * DF + col0 + tx * 4] = v;
        }
    }
}

// ---------------- edge scatter: agg[row] += norm * m[col] ----------------
__global__ void k_scatter(const int* __restrict__ adj_row, const int* __restrict__ adj_col) {
    int e = blockIdx.x * blockDim.y + threadIdx.y;
    if (e >= EE) return;
    int r = adj_row[e], c = adj_col[e];
    float norm = g_dinv[r] * g_dinv[c];
    const float4* src = (const float4*)&g_m[c * DF];
    float4* dst = (float4*)&g_agg[r * DF];
    int lane = threadIdx.x;
#pragma unroll
    for (int i = 0; i < 2; i++) {
        int idx = lane + i * 32;
        float4 v = src[idx];
        asm volatile("red.global.add.v4.f32 [%0], {%1,%2,%3,%4};"
                     :: "l"(dst + idx),
                        "f"(v.x * norm), "f"(v.y * norm), "f"(v.z * norm), "f"(v.w * norm)
                     : "memory");
    }
}

// ---------------- finalize: h = agg + dinv^2 * m + b ----------------
__global__ void k_finalize(const float* __restrict__ b) {
    int t = blockIdx.x * blockDim.x + threadIdx.x;
    if (t >= NN * DF) return;
    int n = t >> 8, j = t & 255;
    float di = g_dinv[n];
    g_h[t] = g_agg[t] + di * di * g_m[t] + b[j];
}

// ---------------- batch norm ----------------
__global__ void k_bn_zero() {
    int j = threadIdx.x;
    g_sum[j] = 0.0; g_sumsq[j] = 0.0;
}
__global__ void k_bn_stats() {
    int j = threadIdx.x;
    int r0 = blockIdx.x * 256;
    float s = 0.f, ss = 0.f;
    int rmax = NN - r0; if (rmax > 256) rmax = 256;
    for (int r = 0; r < rmax; r++) {
        float v = g_h[(r0 + r) * DF + j];
        s += v; ss += v * v;
    }
    atomicAdd(&g_sum[j], (double)s);
    atomicAdd(&g_sumsq[j], (double)ss);
}
__global__ void k_bn_final(const float* __restrict__ gamma, const float* __restrict__ beta) {
    int j = threadIdx.x;
    double mean = g_sum[j] / (double)NN;
    double var = g_sumsq[j] / (double)NN - mean * mean;
    float istd = rsqrtf((float)var + BN_EPS);
    float sc = istd * gamma[j];
    g_scale[j] = sc;
    g_bias[j] = beta[j] - (float)mean * sc;
}
__global__ void k_bn_apply() {
    int t = blockIdx.x * blockDim.x + threadIdx.x;
    if (t >= NN * DF) return;
    int j = t & 255;
    g_h[t] = fmaxf(fmaf(g_h[t], g_scale[j], g_bias[j]), 0.f);
}

// ---------------- fused link predictor ----------------
// per block: 32 queries. z = h[a]*h[b] in smem; thread t owns hidden column t of
// relu(z @ pW1 + pb1); weighted by pW2[t]; cross-thread reduce; sigmoid.
__global__ void k_pred(const int* __restrict__ edges,
                       const float* __restrict__ pW1, const float* __restrict__ pb1,
                       const float* __restrict__ pW2, const float* __restrict__ pb2,
                       float* __restrict__ out) {
    __shared__ float z[32][DF];
    __shared__ float red[32][9];
    const int t = threadIdx.x;                 // 256
    const int q0 = blockIdx.x * 32;

#pragma unroll 4
    for (int r = 0; r < 32; r++) {
        int q = q0 + r;
        int a = edges[q], b = edges[QQ + q];
        z[r][t] = g_h[a * DF + t] * g_h[b * DF + t];
    }
    __syncthreads();

    float acc[32];
#pragma unroll
    for (int r = 0; r < 32; r++) acc[r] = 0.f;

    for (int k = 0; k < DF; k += 4) {
        float w0 = pW1[(k + 0) * DF + t];
        float w1 = pW1[(k + 1) * DF + t];
        float w2 = pW1[(k + 2) * DF + t];
        float w3 = pW1[(k + 3) * DF + t];
#pragma unroll
        for (int r = 0; r < 32; r++) {
            float4 zv = *(const float4*)&z[r][k];
            acc[r] = fmaf(zv.x, w0, acc[r]);
            acc[r] = fmaf(zv.y, w1, acc[r]);
            acc[r] = fmaf(zv.z, w2, acc[r]);
            acc[r] = fmaf(zv.w, w3, acc[r]);
        }
    }

    float pb = pb1[t], pw = pW2[t];
    int lane = t & 31, wid = t >> 5;
#pragma unroll
    for (int r = 0; r < 32; r++) {
        float v = fmaxf(acc[r] + pb, 0.f) * pw;
#pragma unroll
        for (int off = 16; off; off >>= 1) v += __shfl_xor_sync(0xffffffffu, v, off);
        if (lane == 0) red[r][wid] = v;
    }
    __syncthreads();
    if (t < 32) {
        float s = pb2[0];
#pragma unroll
        for (int w = 0; w < 8; w++) s += red[t][w];
        out[q0 + t] = 1.f / (1.f + expf(-s));
    }
}

// ---------------- launch ----------------
extern "C" void kernel_launch(void* const* d_in, const int* in_sizes, int n_in,
                              void* d_out, int out_size) {
    const float* x      = (const float*)d_in[0];
    const int* adj_row  = (const int*)d_in[1];
    const int* adj_col  = (const int*)d_in[2];
    const int* edges    = (const int*)d_in[3];
    const float* emb    = (const float*)d_in[4];
    const float* W1     = (const float*)d_in[5];
    const float* b1     = (const float*)d_in[6];
    const float* W2     = (const float*)d_in[7];
    const float* b2     = (const float*)d_in[8];
    const float* gamma  = (const float*)d_in[9];
    const float* beta   = (const float*)d_in[10];
    const float* pW1    = (const float*)d_in[11];
    const float* pb1    = (const float*)d_in[12];
    const float* pW2    = (const float*)d_in[13];
    const float* pb2    = (const float*)d_in[14];
    float* out = (float*)d_out;

    const int nblk_nd = (NN * DF + 255) / 256;
    const dim3 ggrid(4, (NN + 63) / 64);
    const dim3 sblk(32, 8);
    const int sgrid = (EE + 7) / 8;

    // degrees
    k_zero_deg<<<(NN + 255) / 256, 256>>>();
    k_count<<<(EE + 255) / 256, 256>>>(adj_row);
    k_dinv<<<(NN + 255) / 256, 256>>>();

    // conv1
    k_build_h<<<nblk_nd, 256>>>(x, emb);
    k_gemm<<<ggrid, 256>>>(W1);
    k_zero_agg<<<nblk_nd, 256>>>();
    k_scatter<<<sgrid, sblk>>>(adj_row, adj_col);
    k_finalize<<<nblk_nd, 256>>>(b1);

    // BN + ReLU
    k_bn_zero<<<1, 256>>>();
    k_bn_stats<<<(NN + 255) / 256, 256>>>();
    k_bn_final<<<1, 256>>>(gamma, beta);
    k_bn_apply<<<nblk_nd, 256>>>();

    // conv2
    k_gemm<<<ggrid, 256>>>(W2);
    k_zero_agg<<<nblk_nd, 256>>>();
    k_scatter<<<sgrid, sblk>>>(adj_row, adj_col);
    k_finalize<<<nblk_nd, 256>>>(b2);

    // link predictor
    k_pred<<<(QQ + 31) / 32, 256>>>(edges, pW1, pb1, pW2, pb2, out);
}